// round 3
// baseline (speedup 1.0000x reference)
#include <cuda_runtime.h>

// SharpenedCosineSimilarity forward, fused.
//   y_denorm = conv3x3(x, w / (||w||_2 + eps + q2))
//   y        = y_denorm / (sqrt(box3x3(sum_c x^2) + eps) + q2)
//   out      = sigmoid(y) * (|y| + eps)^(p2)      p2=(p/10)^2, q2=(q/100)^2
//
// Shapes: B=32, Cin=128, Cout=256, H=W=64, K=3, stride=1, pad=1.

#define CIN  128
#define COUT 256
#define HH   64
#define WW   64
#define BB   32
#define TC   64    // couts per block
#define TH   16    // output rows per block
#define TW   16    // output cols per block
#define CK   8     // cin chunk per smem stage
#define EPSF 1e-12f

// ---------------- device scratch (no allocations allowed) ----------------
__device__ float g_wn[CIN * 9 * COUT];   // normalized weights, [cin*9][cout]
__device__ float g_psqr[COUT];           // (p/10)^2
__device__ float g_s[BB * HH * WW];      // per-pixel sum_c x^2
__device__ float g_invden[BB * HH * WW]; // 1 / (sqrt(box3x3(s)+eps) + q2)

// ---------------- f32x2 helpers (Blackwell packed fp32) ----------------
static __device__ __forceinline__ unsigned long long pk2(float a, float b) {
    unsigned long long r;
    asm("mov.b64 %0, {%1, %2};" : "=l"(r) : "f"(a), "f"(b));
    return r;
}
static __device__ __forceinline__ void upk2(unsigned long long v, float& a, float& b) {
    asm("mov.b64 {%0, %1}, %2;" : "=f"(a), "=f"(b) : "l"(v));
}
static __device__ __forceinline__ void fma2(unsigned long long& d,
                                            unsigned long long a,
                                            unsigned long long b) {
    asm("fma.rn.f32x2 %0, %1, %2, %0;" : "+l"(d) : "l"(a), "l"(b));
}

// ---------------- prep kernels ----------------
__global__ void prep_w(const float* __restrict__ w,
                       const float* __restrict__ p,
                       const float* __restrict__ q) {
    __shared__ float red[4];
    const int co = blockIdx.x;
    const int tid = threadIdx.x;
    const float* wr = w + co * 1152;  // [Cout][Cin*3*3]

    float ssum = 0.f;
    for (int i = tid; i < 1152; i += 128) { float v = wr[i]; ssum += v * v; }
    #pragma unroll
    for (int o = 16; o; o >>= 1) ssum += __shfl_xor_sync(0xffffffff, ssum, o);
    if ((tid & 31) == 0) red[tid >> 5] = ssum;
    __syncthreads();
    const float tot = red[0] + red[1] + red[2] + red[3];

    const float qv = q[0] * 0.01f;
    const float qs = qv * qv;
    const float scale = 1.f / (sqrtf(tot) + EPSF + qs);

    // transpose to [cin*9][cout] for vectorized staging in the conv kernel
    for (int i = tid; i < 1152; i += 128)
        g_wn[i * COUT + co] = wr[i] * scale;

    if (tid == 0) { const float pv = p[co] * 0.1f; g_psqr[co] = pv * pv; }
}

__global__ void prep_s(const float* __restrict__ x) {
    const int i = blockIdx.x * 256 + threadIdx.x;  // < B*H*W
    const int b = i >> 12;
    const int hw = i & 4095;
    const float* xp = x + (size_t)b * CIN * 4096 + hw;
    float ssum = 0.f;
    #pragma unroll 8
    for (int c = 0; c < CIN; ++c) { float v = xp[c * 4096]; ssum += v * v; }
    g_s[i] = ssum;
}

__global__ void prep_invden(const float* __restrict__ q) {
    const int i = blockIdx.x * 256 + threadIdx.x;
    const int b = i >> 12;
    const int hw = i & 4095;
    const int h = hw >> 6, w = hw & 63;
    const float* sp = g_s + b * 4096;
    float acc = 0.f;
    #pragma unroll
    for (int dh = -1; dh <= 1; ++dh) {
        const int hh = h + dh;
        if ((unsigned)hh >= (unsigned)HH) continue;
        #pragma unroll
        for (int dw = -1; dw <= 1; ++dw) {
            const int ww2 = w + dw;
            if ((unsigned)ww2 >= (unsigned)WW) continue;
            acc += sp[hh * 64 + ww2];
        }
    }
    const float qv = q[0] * 0.01f;
    const float qs = qv * qv;
    g_invden[i] = 1.f / (sqrtf(acc + EPSF) + qs);
}

// ---------------- fused conv + epilogue ----------------
static __device__ __forceinline__ float scs_act(float y, float psqr) {
    const float sg = 1.f / (1.f + __expf(-y));
    const float mag = exp2f(psqr * __log2f(fabsf(y) + EPSF));
    return sg * mag;
}

// smem union: per-chunk buffers (CK*324 + CK*576 = 7200 floats) vs
// epilogue staging buffer (32*256 = 8192 floats) -> 8192 floats = 32KB static.
#define SMEM_FLOATS 8192

__global__ void __launch_bounds__(256, 2)
conv_kernel(const float* __restrict__ x, float* __restrict__ out) {
    __shared__ float smem[SMEM_FLOATS];
    float* sIn = smem;              // [CK][18][18]
    float* sW  = smem + CK * 324;   // [CK][9][64]

    const int tid = threadIdx.x;
    const int b   = blockIdx.z;
    const int co0 = blockIdx.y * TC;
    const int h0  = (blockIdx.x >> 2) * TH;
    const int w0g = (blockIdx.x & 3) * TW;

    const int cg    = tid >> 5;        // channel group 0..7 (8 couts each)
    const int s     = tid & 31;
    const int row   = s >> 1;          // output row 0..15
    const int wbase = (s & 1) * 8;     // output col base: 0 or 8

    unsigned long long acc[4][8];      // [channel-pair][pixel]
    #pragma unroll
    for (int i = 0; i < 4; ++i)
        #pragma unroll
        for (int j = 0; j < 8; ++j) acc[i][j] = 0ull;

    #pragma unroll 1
    for (int cb = 0; cb < CIN; cb += CK) {
        // ---- stage input tile (with halo, zero-padded) ----
        for (int idx = tid; idx < CK * 324; idx += 256) {
            const int cin = idx / 324;
            const int rem = idx - cin * 324;
            const int r = rem / 18, c = rem - r * 18;
            const int gh = h0 - 1 + r, gw = w0g - 1 + c;
            float v = 0.f;
            if ((unsigned)gh < (unsigned)HH && (unsigned)gw < (unsigned)WW)
                v = x[(((size_t)b * CIN + cb + cin) * HH + gh) * WW + gw];
            sIn[idx] = v;
        }
        // ---- stage weights: [CK][9][64 couts] via float4 ----
        for (int idx = tid; idx < CK * 9 * 16; idx += 256) {
            const int v = idx >> 4;             // (cin*9 + kk)
            const int off = (idx & 15) * 4;     // cout offset within tile
            const float4 w4 =
                *(const float4*)&g_wn[(size_t)(cb * 9 + v) * COUT + co0 + off];
            *(float4*)&sW[v * 64 + off] = w4;
        }
        __syncthreads();

        // ---- compute ----
        #pragma unroll 1
        for (int cin = 0; cin < CK; ++cin) {
            #pragma unroll
            for (int kh = 0; kh < 3; ++kh) {
                const float* ir = &sIn[cin * 324 + (row + kh) * 18 + wbase];
                unsigned long long xd[10];
                #pragma unroll
                for (int j = 0; j < 10; ++j) { const float t = ir[j]; xd[j] = pk2(t, t); }
                const float* wr = &sW[(cin * 9 + kh * 3) * 64 + cg * 8];
                #pragma unroll
                for (int kw = 0; kw < 3; ++kw) {
                    const float4 wa = *(const float4*)(wr + kw * 64);
                    const float4 wb = *(const float4*)(wr + kw * 64 + 4);
                    const unsigned long long wp0 = pk2(wa.x, wa.y);
                    const unsigned long long wp1 = pk2(wa.z, wa.w);
                    const unsigned long long wp2 = pk2(wb.x, wb.y);
                    const unsigned long long wp3 = pk2(wb.z, wb.w);
                    #pragma unroll
                    for (int j = 0; j < 8; ++j) {
                        fma2(acc[0][j], wp0, xd[kw + j]);
                        fma2(acc[1][j], wp1, xd[kw + j]);
                        fma2(acc[2][j], wp2, xd[kw + j]);
                        fma2(acc[3][j], wp3, xd[kw + j]);
                    }
                }
            }
        }
        __syncthreads();
    }

    // ---- epilogue: normalize, activate, stage through smem, coalesced store ----
    float invd[8];
    #pragma unroll
    for (int j = 0; j < 8; ++j)
        invd[j] = g_invden[((size_t)b * HH + h0 + row) * WW + w0g + wbase + j];
    float ps[8];
    #pragma unroll
    for (int cc = 0; cc < 8; ++cc) ps[cc] = g_psqr[co0 + cg * 8 + cc];

    float* stage = smem;  // 8192 floats = [32 ch][256 px]
    #pragma unroll 1
    for (int pass = 0; pass < 2; ++pass) {
        __syncthreads();
        if ((cg >> 2) == pass) {
            const int lcb = (cg & 3) * 8;  // local channel base within 32
            #pragma unroll
            for (int cp = 0; cp < 4; ++cp) {
                #pragma unroll
                for (int j = 0; j < 8; ++j) {
                    float a0, a1;
                    upk2(acc[cp][j], a0, a1);
                    const float y0 = a0 * invd[j];
                    const float y1 = a1 * invd[j];
                    const int sp = row * 16 + wbase + j;
                    stage[(lcb + cp * 2 + 0) * 256 + sp] = scs_act(y0, ps[cp * 2 + 0]);
                    stage[(lcb + cp * 2 + 1) * 256 + sp] = scs_act(y1, ps[cp * 2 + 1]);
                }
            }
        }
        __syncthreads();
        for (int idx = tid; idx < 32 * 256; idx += 256) {
            const int ch = idx >> 8;
            const int sp = idx & 255;
            const int r = sp >> 4, w = sp & 15;
            const int co = co0 + pass * 32 + ch;
            out[(((size_t)b * COUT + co) * HH + h0 + r) * WW + w0g + w] = stage[idx];
        }
    }
}

// ---------------- launch ----------------
extern "C" void kernel_launch(void* const* d_in, const int* in_sizes, int n_in,
                              void* d_out, int out_size) {
    const float *x = nullptr, *w = nullptr, *p = nullptr, *q = nullptr;
    for (int i = 0; i < n_in; ++i) {
        const int sz = in_sizes[i];
        if (sz == BB * CIN * HH * WW)      x = (const float*)d_in[i];
        else if (sz == COUT * CIN * 9)     w = (const float*)d_in[i];
        else if (sz == COUT)               p = (const float*)d_in[i];
        else if (sz == 1)                  q = (const float*)d_in[i];
    }
    float* out = (float*)d_out;

    prep_w<<<COUT, 128>>>(w, p, q);
    prep_s<<<(BB * HH * WW) / 256, 256>>>(x);
    prep_invden<<<(BB * HH * WW) / 256, 256>>>(q);

    dim3 grid(16, 4, 32);  // (4x4 spatial tiles, 4 cout tiles, 32 images)
    conv_kernel<<<grid, 256>>>(x, out);
}